// round 13
// baseline (speedup 1.0000x reference)
#include <cuda_runtime.h>
#include <cuda_bf16.h>
#include <cstdint>

#define CD    256
#define NTOK  32768
#define KCB   8192
#define NELEM 8388608
#define NTILE 64          // KCB / 128
#define WIN   4e-4f       // candidate window (>= 2 * |d~ - d| bound)
#define OVCAP (1 << 21)   // 2M overflow entries

__device__ float g_sz[NTOK];
__device__ float g_en[KCB];
__device__ unsigned long long g_tk[(size_t)NTOK * NTILE]; // per-(token,tile) approx best key
__device__ unsigned long long g_bk[NTOK];                 // exact best key
__device__ float g_th[NTOK];                              // d~min + WIN
__device__ int   g_idx[NTOK];
__device__ unsigned int g_hist[KCB];
__device__ double g_msep[8192];
__device__ __nv_bfloat16 g_zb[(size_t)NTOK * CD];
__device__ __nv_bfloat16 g_eb[(size_t)KCB * CD];
__device__ int  g_ovcnt;
__device__ int4 g_ov[OVCAP];   // {token, code, d~bits, 0}

// ---------------- PTX helpers ----------------
__device__ __forceinline__ void cp16(uint32_t dst, const void* src) {
    asm volatile("cp.async.cg.shared.global [%0], [%1], 16;\n" :: "r"(dst), "l"(src));
}
__device__ __forceinline__ void cp_commit() { asm volatile("cp.async.commit_group;\n" ::); }
__device__ __forceinline__ void cp_wait0()  { asm volatile("cp.async.wait_group 0;\n" ::); }
__device__ __forceinline__ void ldsm4(uint32_t& r0, uint32_t& r1, uint32_t& r2, uint32_t& r3,
                                      uint32_t a) {
    asm volatile("ldmatrix.sync.aligned.m8n8.x4.shared.b16 {%0,%1,%2,%3}, [%4];"
                 : "=r"(r0), "=r"(r1), "=r"(r2), "=r"(r3) : "r"(a));
}
__device__ __forceinline__ void mma16816(float* c, const uint32_t* a, const uint32_t* b) {
    asm volatile("mma.sync.aligned.m16n8k16.row.col.f32.bf16.bf16.f32 "
                 "{%0,%1,%2,%3},{%4,%5,%6,%7},{%8,%9},{%0,%1,%2,%3};"
                 : "+f"(c[0]), "+f"(c[1]), "+f"(c[2]), "+f"(c[3])
                 : "r"(a[0]), "r"(a[1]), "r"(a[2]), "r"(a[3]), "r"(b[0]), "r"(b[1]));
}

// async-copy one K-chunk (64 bf16) of the 128-row A and B tiles (512 threads)
__device__ __forceinline__ void issue_chunk(uint32_t sA_u, uint32_t sB_u,
                                            int buf, int kc, int m0, int n0,
                                            int r_ld, int s_ld) {
    #pragma unroll
    for (int q = 0; q < 2; q++) {
        int r = r_ld + 64 * q;
        int sw = (s_ld ^ (r & 7));
        const uint4* gA = (const uint4*)g_zb + (size_t)(m0 + r) * 32 + kc * 8 + s_ld;
        cp16(sA_u + buf * 16384 + (r * 8 + sw) * 16, gA);
        const uint4* gB = (const uint4*)g_eb + (size_t)(n0 + r) * 32 + kc * 8 + s_ld;
        cp16(sB_u + buf * 16384 + (r * 8 + sw) * 16, gB);
    }
    cp_commit();
}

// ---------------------------------------------------------------------------
// e -> bf16 [KCB][256].  (launch #1)
// ---------------------------------------------------------------------------
__global__ __launch_bounds__(256) void k_cvte(const float* __restrict__ e) {
    size_t i = ((size_t)blockIdx.x * 256 + threadIdx.x) * 8;
    float4 v0 = *(const float4*)(e + i);
    float4 v1 = *(const float4*)(e + i + 4);
    __nv_bfloat16 t[8];
    t[0] = __float2bfloat16(v0.x); t[1] = __float2bfloat16(v0.y);
    t[2] = __float2bfloat16(v0.z); t[3] = __float2bfloat16(v0.w);
    t[4] = __float2bfloat16(v1.x); t[5] = __float2bfloat16(v1.y);
    t[6] = __float2bfloat16(v1.z); t[7] = __float2bfloat16(v1.w);
    *(uint4*)&g_eb[i] = *(uint4*)t;
}

// ---------------------------------------------------------------------------
// Merged z prep (launch #2): one staged read of z feeds BOTH
//  (a) sz[n] — FROZEN arithmetic (identical loads and op order), and
//  (b) the bf16 tokens-major transpose g_zb. Also inits g_bk.
// ---------------------------------------------------------------------------
__global__ __launch_bounds__(256) void k_prep_z(const float* __restrict__ z) {
    __shared__ float zt[CD][10];
    int n0 = blockIdx.x * 8;
    const float* zbase = z + (size_t)(n0 >> 10) * 262144 + (n0 & 1023);

    int wpos  = threadIdx.x & 7;
    int cbase = threadIdx.x >> 3;
    #pragma unroll
    for (int j = 0; j < 8; j++) {
        int c = cbase + 32 * j;
        zt[c][wpos] = zbase[(size_t)c * 1024 + wpos];
    }
    if (threadIdx.x < 8) g_bk[n0 + threadIdx.x] = ~0ull;
    __syncthreads();

    int warp = threadIdx.x >> 5;
    int lane = threadIdx.x & 31;

    // (a) FROZEN sz reduction
    float p = 0.0f;
    #pragma unroll
    for (int j = 0; j < 8; j++) {
        float v = zt[lane + 32 * j][warp];
        p = __fadd_rn(p, __fmul_rn(v, v));
    }
    #pragma unroll
    for (int off = 16; off >= 1; off >>= 1)
        p = __fadd_rn(p, __shfl_down_sync(0xffffffffu, p, off));
    if (lane == 0) g_sz[n0 + warp] = p;

    // (b) bf16 transpose: warp = token, lane covers 8 consecutive channels
    int cc = lane * 8;
    __nv_bfloat16 t8[8];
    #pragma unroll
    for (int i = 0; i < 8; i++)
        t8[i] = __float2bfloat16(zt[cc + i][warp]);
    *(uint4*)&g_zb[(size_t)(n0 + warp) * CD + cc] = *(uint4*)t8;
}

// ---------------------------------------------------------------------------
// en[k] = sum_c e[k,c]^2 — FROZEN. Also zeroes hist and overflow counter.
// (launch #3)
// ---------------------------------------------------------------------------
__global__ __launch_bounds__(256) void k_en(const float* __restrict__ e) {
    int gt = blockIdx.x * 256 + threadIdx.x;
    if (gt < KCB) g_hist[gt] = 0u;
    if (gt == 0)  g_ovcnt = 0;

    int warp = gt >> 5;
    int lane = gt & 31;
    if (warp < KCB) {
        const float* row = e + (size_t)warp * CD;
        float p = 0.0f;
        #pragma unroll
        for (int j = 0; j < 8; j++) {
            float v = row[lane + 32 * j];
            p = __fadd_rn(p, __fmul_rn(v, v));
        }
        #pragma unroll
        for (int off = 16; off >= 1; off >>= 1)
            p = __fadd_rn(p, __shfl_down_sync(0xffffffffu, p, off));
        if (lane == 0) g_en[warp] = p;
    }
}

// ---------------------------------------------------------------------------
// Approximate distance GEMM (bf16 mma.sync) + per-(token,tile) pruning.
// (launch #4 — ncu capture slot)
// Block = 128 tokens x 128 codes, 512 threads, 16 warps as 4(m) x 4(n);
// warp tile 32x32 -> acc 32 regs/thread (target: 64-reg cap, 2 CTAs/SM,
// 32 warps resident). K=256 in 4 chunks of 64 (cp.async double buffer).
// Same kc/j order and fragment mapping as the passing R10/R12 kernel ->
// identical d~ values. Per-(token,tile) best key + overflow within
// tilemin+WIN (superset of all exact-argmin survivors).
// ---------------------------------------------------------------------------
__global__ __launch_bounds__(512, 2) void k_gemm() {
    extern __shared__ char smem[];
    __nv_bfloat16* sA = (__nv_bfloat16*)smem;              // 2 x 16KB
    __nv_bfloat16* sB = (__nv_bfloat16*)(smem + 32768);    // 2 x 16KB
    float* s_en = (float*)(smem + 65536);
    float* s_sz = (float*)(smem + 66048);
    unsigned long long* s_key = (unsigned long long*)(smem + 66560);

    int tid = threadIdx.x;
    int n0 = blockIdx.x * 128, m0 = blockIdx.y * 128;
    if (tid < 128) {
        s_en[tid] = g_en[n0 + tid];
        s_sz[tid] = g_sz[m0 + tid];
        s_key[tid] = ~0ull;
    }

    int l = tid & 31, w = tid >> 5;
    int wy = w >> 2, wx = w & 3;       // 4 m-warps x 4 n-warps
    uint32_t sA_u = (uint32_t)__cvta_generic_to_shared(sA);
    uint32_t sB_u = (uint32_t)__cvta_generic_to_shared(sB);

    int r_ld = tid >> 3, s_ld = tid & 7;

    float acc[2][4][4];
    #pragma unroll
    for (int mf = 0; mf < 2; mf++)
        #pragma unroll
        for (int nf = 0; nf < 4; nf++)
            #pragma unroll
            for (int u = 0; u < 4; u++) acc[mf][nf][u] = 0.0f;

    issue_chunk(sA_u, sB_u, 0, 0, m0, n0, r_ld, s_ld);
    cp_wait0();
    __syncthreads();

    for (int kc = 0; kc < 4; kc++) {
        int cur = kc & 1;
        if (kc < 3) issue_chunk(sA_u, sB_u, cur ^ 1, kc + 1, m0, n0, r_ld, s_ld);

        #pragma unroll
        for (int j = 0; j < 4; j++) {
            int seg = 2 * j + (l >> 4);
            uint32_t a[2][4];
            #pragma unroll
            for (int mf = 0; mf < 2; mf++) {
                int rr = wy * 32 + mf * 16 + (l & 15);
                ldsm4(a[mf][0], a[mf][1], a[mf][2], a[mf][3],
                      sA_u + cur * 16384 + (rr * 8 + (seg ^ (rr & 7))) * 16);
            }
            uint32_t b[4][2];
            #pragma unroll
            for (int p = 0; p < 2; p++) {
                int rr = wx * 32 + p * 16 + (l & 15);
                uint32_t r0, r1, r2, r3;
                ldsm4(r0, r1, r2, r3,
                      sB_u + cur * 16384 + (rr * 8 + (seg ^ (rr & 7))) * 16);
                b[2 * p][0] = r0; b[2 * p + 1][0] = r1;
                b[2 * p][1] = r2; b[2 * p + 1][1] = r3;
            }
            #pragma unroll
            for (int mf = 0; mf < 2; mf++)
                #pragma unroll
                for (int nf = 0; nf < 4; nf++)
                    mma16816(acc[mf][nf], a[mf], b[nf]);
        }
        if (kc < 3) cp_wait0();
        __syncthreads();
    }

    // ---- epilogue: d~ = fl(fl(sz - fl(2m~)) + en); per-row min + overflow ----
    int t4 = l & 3, g8 = l >> 2;

    #pragma unroll
    for (int mf = 0; mf < 2; mf++) {
        #pragma unroll
        for (int hl = 0; hl < 2; hl++) {
            int row_l = wy * 32 + mf * 16 + hl * 8 + g8;
            float szv = s_sz[row_l];
            unsigned long long best = ~0ull;
            #pragma unroll
            for (int nf = 0; nf < 4; nf++) {
                #pragma unroll
                for (int u = 0; u < 2; u++) {
                    int col_l = wx * 32 + nf * 8 + 2 * t4 + u;
                    float mt = acc[mf][nf][hl * 2 + u];
                    float d = __fadd_rn(__fsub_rn(szv, __fmul_rn(2.0f, mt)), s_en[col_l]);
                    acc[mf][nf][hl * 2 + u] = d;
                    unsigned long long key =
                        ((unsigned long long)__float_as_uint(d) << 32) |
                        (unsigned int)(n0 + col_l);
                    if (key < best) best = key;
                }
            }
            best = min(best, __shfl_xor_sync(0xffffffffu, best, 1));
            best = min(best, __shfl_xor_sync(0xffffffffu, best, 2));
            if (t4 == 0) atomicMin(&s_key[row_l], best);
        }
    }
    __syncthreads();

    #pragma unroll
    for (int mf = 0; mf < 2; mf++) {
        #pragma unroll
        for (int hl = 0; hl < 2; hl++) {
            int row_l = wy * 32 + mf * 16 + hl * 8 + g8;
            unsigned long long bk = s_key[row_l];
            float th = __fadd_rn(__uint_as_float((uint32_t)(bk >> 32)), WIN);
            #pragma unroll
            for (int nf = 0; nf < 4; nf++) {
                #pragma unroll
                for (int u = 0; u < 2; u++) {
                    float d = acc[mf][nf][hl * 2 + u];
                    int gidx = n0 + wx * 32 + nf * 8 + 2 * t4 + u;
                    unsigned long long key =
                        ((unsigned long long)__float_as_uint(d) << 32) | (unsigned int)gidx;
                    if (d <= th && key != bk) {
                        int pos = atomicAdd(&g_ovcnt, 1);
                        if (pos < OVCAP)
                            g_ov[pos] = make_int4(m0 + row_l, gidx, __float_as_int(d), 0);
                    }
                }
            }
        }
    }

    if (tid < 128)
        g_tk[(size_t)(m0 + tid) * NTILE + blockIdx.x] = s_key[tid];
}

// ---------------------------------------------------------------------------
// Exact distance (FROZEN): single fmaf chain c ascending, exact epilogue.
// ---------------------------------------------------------------------------
__device__ __forceinline__ float rescore(const float* __restrict__ z,
                                         const float* __restrict__ e,
                                         int n, int k) {
    int b = n >> 10, hw = n & 1023;
    const float* zr = z + (size_t)b * 262144 + hw;
    const float* er = e + (size_t)k * CD;
    float m = 0.0f;
    #pragma unroll 8
    for (int c = 0; c < CD; c++)
        m = __fmaf_rn(zr[(size_t)c * 1024], er[c], m);
    return __fadd_rn(__fsub_rn(g_sz[n], __fmul_rn(2.0f, m)), g_en[k]);
}

// ---------------------------------------------------------------------------
// Per token: global approx min over tiles, rescore qualifying tile winners.
// ---------------------------------------------------------------------------
__global__ __launch_bounds__(256) void k_reduce2(const float* __restrict__ z,
                                                 const float* __restrict__ e) {
    int n = blockIdx.x * 256 + threadIdx.x;
    if (n >= NTOK) return;
    const unsigned long long* tk = g_tk + (size_t)n * NTILE;
    unsigned long long am = ~0ull;
    #pragma unroll 8
    for (int t = 0; t < NTILE; t++) am = min(am, tk[t]);
    float th = __fadd_rn(__uint_as_float((uint32_t)(am >> 32)), WIN);
    g_th[n] = th;

    unsigned long long best = ~0ull;
    for (int t = 0; t < NTILE; t++) {
        unsigned long long k = tk[t];
        if (__uint_as_float((uint32_t)(k >> 32)) <= th) {
            int idx = (int)(k & 0xffffffffull);
            float d = rescore(z, e, n, idx);
            unsigned long long key =
                ((unsigned long long)__float_as_uint(d) << 32) | (unsigned int)idx;
            if (key < best) best = key;
        }
    }
    g_bk[n] = best;
}

// ---------------------------------------------------------------------------
// Rescore qualifying overflow candidates (grid-stride), atomicMin merge.
// ---------------------------------------------------------------------------
__global__ __launch_bounds__(256) void k_over(const float* __restrict__ z,
                                              const float* __restrict__ e) {
    int cnt = g_ovcnt;
    if (cnt > OVCAP) cnt = OVCAP;
    for (int i = blockIdx.x * 256 + threadIdx.x; i < cnt; i += gridDim.x * 256) {
        int4 ev = g_ov[i];
        if (__int_as_float(ev.z) <= g_th[ev.x]) {
            float d = rescore(z, e, ev.x, ev.y);
            unsigned long long key =
                ((unsigned long long)__float_as_uint(d) << 32) | (unsigned int)ev.y;
            atomicMin(&g_bk[ev.x], key);
        }
    }
}

// ---------------------------------------------------------------------------
// Finalize indices: g_idx, histogram, float index output.
// ---------------------------------------------------------------------------
__global__ __launch_bounds__(256) void k_hist(float* __restrict__ out_idx, int write_idx) {
    int n = blockIdx.x * 256 + threadIdx.x;
    if (n >= NTOK) return;
    int idx = (int)(g_bk[n] & 0xffffffffull);
    g_idx[n] = idx;
    atomicAdd(&g_hist[idx], 1u);
    if (write_idx) out_idx[n] = (float)idx;
}

// ---------------------------------------------------------------------------
// z_q_st = fl(z + fl(z_q - z)); per-block mse partial in double.  (FROZEN)
// ---------------------------------------------------------------------------
__global__ __launch_bounds__(1024) void k_zq(const float* __restrict__ z,
                                             const float* __restrict__ e,
                                             float* __restrict__ out) {
    __shared__ double red[1024];
    int f = blockIdx.x * 1024 + threadIdx.x;
    int bc = f >> 10;
    int hw = f & 1023;
    int bb = bc >> 8;
    int c  = bc & 255;
    int n  = bb * 1024 + hw;

    float zv = z[f];
    float zq = e[(size_t)g_idx[n] * CD + c];
    float t  = __fsub_rn(zq, zv);
    out[f]   = __fadd_rn(zv, t);
    float dm = __fsub_rn(zv, zq);
    red[threadIdx.x] = (double)dm * (double)dm;
    __syncthreads();
    for (int s = 512; s >= 1; s >>= 1) {
        if (threadIdx.x < s) red[threadIdx.x] += red[threadIdx.x + s];
        __syncthreads();
    }
    if (threadIdx.x == 0) g_msep[blockIdx.x] = red[0];
}

__global__ __launch_bounds__(256) void k_final(float* __restrict__ out_scalars) {
    __shared__ double red[256];
    int t = threadIdx.x;

    double s = 0.0;
    for (int i = t; i < 8192; i += 256) s += g_msep[i];
    red[t] = s;
    __syncthreads();
    for (int st = 128; st >= 1; st >>= 1) {
        if (t < st) red[t] += red[t + st];
        __syncthreads();
    }
    double mse = red[0] / (double)NELEM;

    double ent = 0.0;
    for (int k = t; k < KCB; k += 256) {
        unsigned int c = g_hist[k];
        if (c) {
            double p = (double)c / (double)NTOK;
            ent += p * log(p);
        }
    }
    __syncthreads();
    red[t] = ent;
    __syncthreads();
    for (int st = 128; st >= 1; st >>= 1) {
        if (t < st) red[t] += red[t + st];
        __syncthreads();
    }
    if (t == 0) {
        out_scalars[0] = __fmul_rn(1.25f, (float)mse);
        out_scalars[1] = (float)exp(-red[0]);
    }
}

extern "C" void kernel_launch(void* const* d_in, const int* in_sizes, int n_in,
                              void* d_out, int out_size) {
    const float* z = (const float*)d_in[0];
    const float* e = (const float*)d_in[1];
    float* out = (float*)d_out;

    int full = (out_size >= NELEM + 2 + NTOK) ? 1 : 0;
    float* out_scalars = out + NELEM;
    float* out_idx     = out + NELEM + 2;

    cudaFuncSetAttribute(k_gemm, cudaFuncAttributeMaxDynamicSharedMemorySize, 67584);

    k_cvte<<<(KCB * CD / 8) / 256, 256>>>(e);   // #1
    k_prep_z<<<NTOK / 8, 256>>>(z);             // #2 (sz + bf16 transpose)
    k_en<<<KCB * 32 / 256, 256>>>(e);           // #3
    {
        dim3 grid(KCB / 128, NTOK / 128);
        k_gemm<<<grid, 512, 67584>>>();         // #4  <- ncu capture slot
    }
    k_reduce2<<<NTOK / 256, 256>>>(z, e);       // #5
    k_over<<<512, 256>>>(z, e);                 // #6
    k_hist<<<NTOK / 256, 256>>>(full ? out_idx : (float*)d_out, full); // #7
    k_zq<<<NELEM / 1024, 1024>>>(z, e, out);    // #8
    if (full) k_final<<<1, 256>>>(out_scalars); // #9
}

// round 15
// speedup vs baseline: 1.2406x; 1.2406x over previous
#include <cuda_runtime.h>
#include <cuda_bf16.h>
#include <cstdint>

#define CD    256
#define NTOK  32768
#define KCB   8192
#define NELEM 8388608
#define NTILE 64          // KCB / 128
#define WIN   4e-4f       // candidate window (>= 2 * |d~ - d| bound)
#define OVCAP (1 << 21)   // 2M overflow entries
#define NZQB  2048        // k_zq blocks (16 tokens each)

__device__ float g_sz[NTOK];
__device__ float g_en[KCB];
__device__ float g_zt[(size_t)NTOK * CD];                 // fp32 token-major z copy
__device__ unsigned long long g_tk[(size_t)NTILE * NTOK]; // [tile][token] approx best key
__device__ unsigned long long g_bk[NTOK];                 // exact best key
__device__ float g_th[NTOK];                              // d~min + WIN
__device__ int   g_idx[NTOK];
__device__ unsigned int g_hist[KCB];
__device__ double g_msep[NZQB];
__device__ __nv_bfloat16 g_zb[(size_t)NTOK * CD];
__device__ __nv_bfloat16 g_eb[(size_t)KCB * CD];
__device__ int  g_ovcnt;
__device__ int4 g_ov[OVCAP];   // {token, code, d~bits, 0}

// ---------------- PTX helpers ----------------
__device__ __forceinline__ void cp16(uint32_t dst, const void* src) {
    asm volatile("cp.async.cg.shared.global [%0], [%1], 16;\n" :: "r"(dst), "l"(src));
}
__device__ __forceinline__ void cp_commit() { asm volatile("cp.async.commit_group;\n" ::); }
__device__ __forceinline__ void cp_wait0()  { asm volatile("cp.async.wait_group 0;\n" ::); }
__device__ __forceinline__ void ldsm4(uint32_t& r0, uint32_t& r1, uint32_t& r2, uint32_t& r3,
                                      uint32_t a) {
    asm volatile("ldmatrix.sync.aligned.m8n8.x4.shared.b16 {%0,%1,%2,%3}, [%4];"
                 : "=r"(r0), "=r"(r1), "=r"(r2), "=r"(r3) : "r"(a));
}
__device__ __forceinline__ void mma16816(float* c, const uint32_t* a, const uint32_t* b) {
    asm volatile("mma.sync.aligned.m16n8k16.row.col.f32.bf16.bf16.f32 "
                 "{%0,%1,%2,%3},{%4,%5,%6,%7},{%8,%9},{%0,%1,%2,%3};"
                 : "+f"(c[0]), "+f"(c[1]), "+f"(c[2]), "+f"(c[3])
                 : "r"(a[0]), "r"(a[1]), "r"(a[2]), "r"(a[3]), "r"(b[0]), "r"(b[1]));
}

// async-copy one K-chunk (64 bf16) of the 128-row A and B tiles (256 threads)
__device__ __forceinline__ void issue_chunk(uint32_t sA_u, uint32_t sB_u,
                                            int buf, int kc, int m0, int n0,
                                            int r_ld, int s_ld) {
    #pragma unroll
    for (int q = 0; q < 4; q++) {
        int r = r_ld + 32 * q;
        int sw = (s_ld ^ (r & 7));
        const uint4* gA = (const uint4*)g_zb + (size_t)(m0 + r) * 32 + kc * 8 + s_ld;
        cp16(sA_u + buf * 16384 + (r * 8 + sw) * 16, gA);
        const uint4* gB = (const uint4*)g_eb + (size_t)(n0 + r) * 32 + kc * 8 + s_ld;
        cp16(sB_u + buf * 16384 + (r * 8 + sw) * 16, gB);
    }
    cp_commit();
}

// ---------------------------------------------------------------------------
// e -> bf16 [KCB][256].  (launch #1)
// ---------------------------------------------------------------------------
__global__ __launch_bounds__(256) void k_cvte(const float* __restrict__ e) {
    size_t i = ((size_t)blockIdx.x * 256 + threadIdx.x) * 8;
    float4 v0 = *(const float4*)(e + i);
    float4 v1 = *(const float4*)(e + i + 4);
    __nv_bfloat16 t[8];
    t[0] = __float2bfloat16(v0.x); t[1] = __float2bfloat16(v0.y);
    t[2] = __float2bfloat16(v0.z); t[3] = __float2bfloat16(v0.w);
    t[4] = __float2bfloat16(v1.x); t[5] = __float2bfloat16(v1.y);
    t[6] = __float2bfloat16(v1.z); t[7] = __float2bfloat16(v1.w);
    *(uint4*)&g_eb[i] = *(uint4*)t;
}

// ---------------------------------------------------------------------------
// Merged z prep (launch #2): one staged read of z feeds
//  (a) sz[n] — FROZEN arithmetic (identical loads and op order),
//  (b) bf16 tokens-major transpose g_zb,
//  (c) fp32 tokens-major copy g_zt (for coalesced exact rescore).
// Also inits g_bk.
// ---------------------------------------------------------------------------
__global__ __launch_bounds__(256) void k_prep_z(const float* __restrict__ z) {
    __shared__ float zt[CD][10];
    int n0 = blockIdx.x * 8;
    const float* zbase = z + (size_t)(n0 >> 10) * 262144 + (n0 & 1023);

    int wpos  = threadIdx.x & 7;
    int cbase = threadIdx.x >> 3;
    #pragma unroll
    for (int j = 0; j < 8; j++) {
        int c = cbase + 32 * j;
        zt[c][wpos] = zbase[(size_t)c * 1024 + wpos];
    }
    if (threadIdx.x < 8) g_bk[n0 + threadIdx.x] = ~0ull;
    __syncthreads();

    int warp = threadIdx.x >> 5;
    int lane = threadIdx.x & 31;

    // (a) FROZEN sz reduction
    float p = 0.0f;
    #pragma unroll
    for (int j = 0; j < 8; j++) {
        float v = zt[lane + 32 * j][warp];
        p = __fadd_rn(p, __fmul_rn(v, v));
    }
    #pragma unroll
    for (int off = 16; off >= 1; off >>= 1)
        p = __fadd_rn(p, __shfl_down_sync(0xffffffffu, p, off));
    if (lane == 0) g_sz[n0 + warp] = p;

    // (b)+(c): warp = token, lane covers 8 consecutive channels
    int cc = lane * 8;
    float tf[8];
    __nv_bfloat16 t8[8];
    #pragma unroll
    for (int i = 0; i < 8; i++) {
        tf[i] = zt[cc + i][warp];
        t8[i] = __float2bfloat16(tf[i]);
    }
    *(uint4*)&g_zb[(size_t)(n0 + warp) * CD + cc] = *(uint4*)t8;
    float* zrow = &g_zt[(size_t)(n0 + warp) * CD + cc];
    *(float4*)zrow       = make_float4(tf[0], tf[1], tf[2], tf[3]);
    *(float4*)(zrow + 4) = make_float4(tf[4], tf[5], tf[6], tf[7]);
}

// ---------------------------------------------------------------------------
// en[k] = sum_c e[k,c]^2 — FROZEN. Also zeroes hist and overflow counter.
// (launch #3)
// ---------------------------------------------------------------------------
__global__ __launch_bounds__(256) void k_en(const float* __restrict__ e) {
    int gt = blockIdx.x * 256 + threadIdx.x;
    if (gt < KCB) g_hist[gt] = 0u;
    if (gt == 0)  g_ovcnt = 0;

    int warp = gt >> 5;
    int lane = gt & 31;
    if (warp < KCB) {
        const float* row = e + (size_t)warp * CD;
        float p = 0.0f;
        #pragma unroll
        for (int j = 0; j < 8; j++) {
            float v = row[lane + 32 * j];
            p = __fadd_rn(p, __fmul_rn(v, v));
        }
        #pragma unroll
        for (int off = 16; off >= 1; off >>= 1)
            p = __fadd_rn(p, __shfl_down_sync(0xffffffffu, p, off));
        if (lane == 0) g_en[warp] = p;
    }
}

// ---------------------------------------------------------------------------
// Approximate distance GEMM (bf16 mma.sync) + per-(token,tile) pruning.
// (launch #4 — ncu capture slot)  == R12's passing kernel; only the g_tk
// write is transposed to [tile][token] for coalescing.
// ---------------------------------------------------------------------------
__global__ __launch_bounds__(256, 2) void k_gemm() {
    extern __shared__ char smem[];
    __nv_bfloat16* sA = (__nv_bfloat16*)smem;              // 2 x 16KB
    __nv_bfloat16* sB = (__nv_bfloat16*)(smem + 32768);    // 2 x 16KB
    float* s_en = (float*)(smem + 65536);
    float* s_sz = (float*)(smem + 66048);
    unsigned long long* s_key = (unsigned long long*)(smem + 66560);

    int tid = threadIdx.x;
    int n0 = blockIdx.x * 128, m0 = blockIdx.y * 128;
    if (tid < 128) {
        s_en[tid] = g_en[n0 + tid];
        s_sz[tid] = g_sz[m0 + tid];
        s_key[tid] = ~0ull;
    }

    int l = tid & 31, w = tid >> 5;
    int wy = w & 3, wx = w >> 2;
    uint32_t sA_u = (uint32_t)__cvta_generic_to_shared(sA);
    uint32_t sB_u = (uint32_t)__cvta_generic_to_shared(sB);

    int r_ld = tid >> 3, s_ld = tid & 7;

    float acc[2][8][4];
    #pragma unroll
    for (int mf = 0; mf < 2; mf++)
        #pragma unroll
        for (int nf = 0; nf < 8; nf++)
            #pragma unroll
            for (int u = 0; u < 4; u++) acc[mf][nf][u] = 0.0f;

    issue_chunk(sA_u, sB_u, 0, 0, m0, n0, r_ld, s_ld);
    cp_wait0();
    __syncthreads();

    for (int kc = 0; kc < 4; kc++) {
        int cur = kc & 1;
        if (kc < 3) issue_chunk(sA_u, sB_u, cur ^ 1, kc + 1, m0, n0, r_ld, s_ld);

        #pragma unroll
        for (int j = 0; j < 4; j++) {
            int seg = 2 * j + (l >> 4);
            uint32_t a[2][4];
            #pragma unroll
            for (int mf = 0; mf < 2; mf++) {
                int rr = wy * 32 + mf * 16 + (l & 15);
                ldsm4(a[mf][0], a[mf][1], a[mf][2], a[mf][3],
                      sA_u + cur * 16384 + (rr * 8 + (seg ^ (rr & 7))) * 16);
            }
            uint32_t b[8][2];
            #pragma unroll
            for (int p = 0; p < 4; p++) {
                int rr = wx * 64 + p * 16 + (l & 15);
                uint32_t r0, r1, r2, r3;
                ldsm4(r0, r1, r2, r3,
                      sB_u + cur * 16384 + (rr * 8 + (seg ^ (rr & 7))) * 16);
                b[2 * p][0] = r0; b[2 * p + 1][0] = r1;
                b[2 * p][1] = r2; b[2 * p + 1][1] = r3;
            }
            #pragma unroll
            for (int mf = 0; mf < 2; mf++)
                #pragma unroll
                for (int nf = 0; nf < 8; nf++)
                    mma16816(acc[mf][nf], a[mf], b[nf]);
        }
        if (kc < 3) cp_wait0();
        __syncthreads();
    }

    // ---- epilogue: d~ = fl(fl(sz - fl(2m~)) + en); per-row min + overflow ----
    int t4 = l & 3, g8 = l >> 2;

    #pragma unroll
    for (int mf = 0; mf < 2; mf++) {
        #pragma unroll
        for (int hl = 0; hl < 2; hl++) {
            int row_l = wy * 32 + mf * 16 + hl * 8 + g8;
            float szv = s_sz[row_l];
            unsigned long long best = ~0ull;
            #pragma unroll
            for (int nf = 0; nf < 8; nf++) {
                #pragma unroll
                for (int u = 0; u < 2; u++) {
                    int col_l = wx * 64 + nf * 8 + 2 * t4 + u;
                    float mt = acc[mf][nf][hl * 2 + u];
                    float d = __fadd_rn(__fsub_rn(szv, __fmul_rn(2.0f, mt)), s_en[col_l]);
                    acc[mf][nf][hl * 2 + u] = d;
                    unsigned long long key =
                        ((unsigned long long)__float_as_uint(d) << 32) |
                        (unsigned int)(n0 + col_l);
                    if (key < best) best = key;
                }
            }
            best = min(best, __shfl_xor_sync(0xffffffffu, best, 1));
            best = min(best, __shfl_xor_sync(0xffffffffu, best, 2));
            if (t4 == 0) atomicMin(&s_key[row_l], best);
        }
    }
    __syncthreads();

    #pragma unroll
    for (int mf = 0; mf < 2; mf++) {
        #pragma unroll
        for (int hl = 0; hl < 2; hl++) {
            int row_l = wy * 32 + mf * 16 + hl * 8 + g8;
            unsigned long long bk = s_key[row_l];
            float th = __fadd_rn(__uint_as_float((uint32_t)(bk >> 32)), WIN);
            #pragma unroll
            for (int nf = 0; nf < 8; nf++) {
                #pragma unroll
                for (int u = 0; u < 2; u++) {
                    float d = acc[mf][nf][hl * 2 + u];
                    int gidx = n0 + wx * 64 + nf * 8 + 2 * t4 + u;
                    unsigned long long key =
                        ((unsigned long long)__float_as_uint(d) << 32) | (unsigned int)gidx;
                    if (d <= th && key != bk) {
                        int pos = atomicAdd(&g_ovcnt, 1);
                        if (pos < OVCAP)
                            g_ov[pos] = make_int4(m0 + row_l, gidx, __float_as_int(d), 0);
                    }
                }
            }
        }
    }

    if (tid < 128)
        g_tk[(size_t)blockIdx.x * NTOK + (m0 + tid)] = s_key[tid];
}

// ---------------------------------------------------------------------------
// Exact distance (FROZEN chain): single fmaf chain c ascending over the
// token-major fp32 copy (same values, same op order, coalesced reads).
// ---------------------------------------------------------------------------
__device__ __forceinline__ float rescore(const float* __restrict__ e,
                                         int n, int k) {
    const float* zr = g_zt + (size_t)n * CD;
    const float* er = e + (size_t)k * CD;
    float m = 0.0f;
    #pragma unroll 8
    for (int c = 0; c < CD; c++)
        m = __fmaf_rn(zr[c], er[c], m);
    return __fadd_rn(__fsub_rn(g_sz[n], __fmul_rn(2.0f, m)), g_en[k]);
}

// ---------------------------------------------------------------------------
// Per token: global approx min over tiles, rescore qualifying tile winners.
// ---------------------------------------------------------------------------
__global__ __launch_bounds__(256) void k_reduce2(const float* __restrict__ e) {
    int n = blockIdx.x * 256 + threadIdx.x;
    if (n >= NTOK) return;
    unsigned long long am = ~0ull;
    #pragma unroll 8
    for (int t = 0; t < NTILE; t++) am = min(am, g_tk[(size_t)t * NTOK + n]);
    float th = __fadd_rn(__uint_as_float((uint32_t)(am >> 32)), WIN);
    g_th[n] = th;

    unsigned long long best = ~0ull;
    for (int t = 0; t < NTILE; t++) {
        unsigned long long k = g_tk[(size_t)t * NTOK + n];
        if (__uint_as_float((uint32_t)(k >> 32)) <= th) {
            int idx = (int)(k & 0xffffffffull);
            float d = rescore(e, n, idx);
            unsigned long long key =
                ((unsigned long long)__float_as_uint(d) << 32) | (unsigned int)idx;
            if (key < best) best = key;
        }
    }
    g_bk[n] = best;
}

// ---------------------------------------------------------------------------
// Rescore qualifying overflow candidates (grid-stride), atomicMin merge.
// ---------------------------------------------------------------------------
__global__ __launch_bounds__(256) void k_over(const float* __restrict__ e) {
    int cnt = g_ovcnt;
    if (cnt > OVCAP) cnt = OVCAP;
    for (int i = blockIdx.x * 256 + threadIdx.x; i < cnt; i += gridDim.x * 256) {
        int4 ev = g_ov[i];
        if (__int_as_float(ev.z) <= g_th[ev.x]) {
            float d = rescore(e, ev.x, ev.y);
            unsigned long long key =
                ((unsigned long long)__float_as_uint(d) << 32) | (unsigned int)ev.y;
            atomicMin(&g_bk[ev.x], key);
        }
    }
}

// ---------------------------------------------------------------------------
// Finalize indices: g_idx, histogram, float index output.
// ---------------------------------------------------------------------------
__global__ __launch_bounds__(256) void k_hist(float* __restrict__ out_idx, int write_idx) {
    int n = blockIdx.x * 256 + threadIdx.x;
    if (n >= NTOK) return;
    int idx = (int)(g_bk[n] & 0xffffffffull);
    g_idx[n] = idx;
    atomicAdd(&g_hist[idx], 1u);
    if (write_idx) out_idx[n] = (float)idx;
}

// ---------------------------------------------------------------------------
// z_q_st = fl(z + fl(z_q - z)) — FROZEN ops, new access pattern:
// block = 16 tokens; stage their e rows in smem (coalesced row loads),
// then stream z/out in z-layout (coalesced). Pad 265 -> conflict-free.
// Per-block mse partial in double.
// ---------------------------------------------------------------------------
__global__ __launch_bounds__(256) void k_zq(const float* __restrict__ z,
                                            const float* __restrict__ e,
                                            float* __restrict__ out) {
    __shared__ float s_e[16][265];
    __shared__ int   s_idx[16];
    __shared__ double red[256];

    int tid = threadIdx.x;
    int n0 = blockIdx.x * 16;
    int b  = n0 >> 10;
    int hw0 = n0 & 1023;

    if (tid < 16) s_idx[tid] = g_idx[n0 + tid];
    __syncthreads();

    // stage 16 e-rows: warp w loads rows 2w, 2w+1; lane covers 8 floats
    {
        int w = tid >> 5, l = tid & 31;
        #pragma unroll
        for (int rr = 0; rr < 2; rr++) {
            int row = 2 * w + rr;
            const float* src = e + (size_t)s_idx[row] * CD + l * 8;
            float4 v0 = *(const float4*)src;
            float4 v1 = *(const float4*)(src + 4);
            float* dst = &s_e[row][l * 8];
            dst[0] = v0.x; dst[1] = v0.y; dst[2] = v0.z; dst[3] = v0.w;
            dst[4] = v1.x; dst[5] = v1.y; dst[6] = v1.z; dst[7] = v1.w;
        }
    }
    __syncthreads();

    // main: 16 tokens x 256 channels = 4096 elems, 16 iters of 256
    double acc = 0.0;
    const float* zb = z + (size_t)b * 262144 + hw0;
    float* ob = out + (size_t)b * 262144 + hw0;
    #pragma unroll 4
    for (int it = 0; it < 16; it++) {
        int m = it * 256 + tid;
        int tok = m & 15;
        int c   = m >> 4;
        size_t off = (size_t)c * 1024 + tok;
        float zv = zb[off];
        float zq = s_e[tok][c];
        float t  = __fsub_rn(zq, zv);
        ob[off]  = __fadd_rn(zv, t);
        float dm = __fsub_rn(zv, zq);
        acc += (double)dm * (double)dm;
    }

    red[tid] = acc;
    __syncthreads();
    for (int s = 128; s >= 1; s >>= 1) {
        if (tid < s) red[tid] += red[tid + s];
        __syncthreads();
    }
    if (tid == 0) g_msep[blockIdx.x] = red[0];
}

__global__ __launch_bounds__(256) void k_final(float* __restrict__ out_scalars) {
    __shared__ double red[256];
    int t = threadIdx.x;

    double s = 0.0;
    for (int i = t; i < NZQB; i += 256) s += g_msep[i];
    red[t] = s;
    __syncthreads();
    for (int st = 128; st >= 1; st >>= 1) {
        if (t < st) red[t] += red[t + st];
        __syncthreads();
    }
    double mse = red[0] / (double)NELEM;

    double ent = 0.0;
    for (int k = t; k < KCB; k += 256) {
        unsigned int c = g_hist[k];
        if (c) {
            double p = (double)c / (double)NTOK;
            ent += p * log(p);
        }
    }
    __syncthreads();
    red[t] = ent;
    __syncthreads();
    for (int st = 128; st >= 1; st >>= 1) {
        if (t < st) red[t] += red[t + st];
        __syncthreads();
    }
    if (t == 0) {
        out_scalars[0] = __fmul_rn(1.25f, (float)mse);
        out_scalars[1] = (float)exp(-red[0]);
    }
}

extern "C" void kernel_launch(void* const* d_in, const int* in_sizes, int n_in,
                              void* d_out, int out_size) {
    const float* z = (const float*)d_in[0];
    const float* e = (const float*)d_in[1];
    float* out = (float*)d_out;

    int full = (out_size >= NELEM + 2 + NTOK) ? 1 : 0;
    float* out_scalars = out + NELEM;
    float* out_idx     = out + NELEM + 2;

    cudaFuncSetAttribute(k_gemm, cudaFuncAttributeMaxDynamicSharedMemorySize, 67584);

    k_cvte<<<(KCB * CD / 8) / 256, 256>>>(e);   // #1
    k_prep_z<<<NTOK / 8, 256>>>(z);             // #2 (sz + bf16 + fp32 transpose)
    k_en<<<KCB * 32 / 256, 256>>>(e);           // #3
    {
        dim3 grid(KCB / 128, NTOK / 128);
        k_gemm<<<grid, 256, 67584>>>();         // #4  <- ncu capture slot
    }
    k_reduce2<<<NTOK / 256, 256>>>(e);          // #5
    k_over<<<512, 256>>>(e);                    // #6
    k_hist<<<NTOK / 256, 256>>>(full ? out_idx : (float*)d_out, full); // #7
    k_zq<<<NZQB, 256>>>(z, e, out);             // #8
    if (full) k_final<<<1, 256>>>(out_scalars); // #9
}